// round 1
// baseline (speedup 1.0000x reference)
#include <cuda_runtime.h>
#include <cuda_bf16.h>

// RNN: out[n,t,:] = tanh(x[n,t,:]@Wx + b + h_{t-1}@Wh), h_{-1}=h0.
// N=64, T=512, D=256, H=256, all fp32.
//
// Kernel 1: xW = x@Wx + b  (32768x256 @ 256x256) -> scratch g_xw, SIMT fp32
//           with packed fma.rn.f32x2 (2 FMAs/issue).
// Kernel 2: recurrence. 128 CTAs = 64 batches x 2-CTA cluster. Each CTA owns
//           128 output columns with its Wh slice (256x128 fp32) register-
//           resident as f32x2 pairs. Per step: h@Wh partials (f32x2 chain),
//           combine + tanh, write local h half + DSMEM-store to peer +
//           mbarrier arrive (release.cluster); wait peer's 128 arrivals
//           (acquire.cluster) before next step.

#define ULL unsigned long long

static __device__ __forceinline__ ULL pk2(float lo, float hi) {
    ULL r; asm("mov.b64 %0, {%1,%2};" : "=l"(r) : "f"(lo), "f"(hi)); return r;
}
static __device__ __forceinline__ void upk2(ULL v, float& lo, float& hi) {
    asm("mov.b64 {%0,%1}, %2;" : "=f"(lo), "=f"(hi) : "l"(v));
}
static __device__ __forceinline__ ULL f2fma(ULL a, ULL b, ULL c) {
    ULL d; asm("fma.rn.f32x2 %0, %1, %2, %3;" : "=l"(d) : "l"(a), "l"(b), "l"(c)); return d;
}
static __device__ __forceinline__ ULL f2add(ULL a, ULL b) {
    ULL d; asm("add.rn.f32x2 %0, %1, %2;" : "=l"(d) : "l"(a), "l"(b)); return d;
}
static __device__ __forceinline__ unsigned int smem_u32(const void* p) {
    unsigned int a;
    asm("{ .reg .u64 t; cvta.to.shared.u64 t, %1; cvt.u32.u64 %0, t; }"
        : "=r"(a) : "l"(p));
    return a;
}

// Scratch for the input projection (no cudaMalloc allowed).
__device__ float g_xw[64 * 512 * 256];

// ---------------------------------------------------------------------------
// Kernel 1: xW GEMM.  C[M=32768, H=256] = X[M,256] * Wx[256,256] + b
// Block 256 thr, tile 128(M) x 128(H), BK=16. Micro-tile per thread:
// 16 rows (warp) x 4 cols (lane), accumulated as f32x2 pairs along M.
// ---------------------------------------------------------------------------
__global__ void __launch_bounds__(256) gemm_xw(const float* __restrict__ X,
                                               const float* __restrict__ Wx,
                                               const float* __restrict__ bias) {
    __shared__ __align__(16) float As[16][128];  // [k][m]  (transposed store)
    __shared__ __align__(16) float Bs[16][128];  // [k][h]

    const int t    = threadIdx.x;
    const int m0   = blockIdx.x * 128;
    const int h0   = blockIdx.y * 128;
    const int warp = t >> 5;
    const int lane = t & 31;

    ULL acc[8][4];
#pragma unroll
    for (int p = 0; p < 8; p++)
#pragma unroll
        for (int c = 0; c < 4; c++) acc[p][c] = 0ULL;

    for (int k0 = 0; k0 < 256; k0 += 16) {
        // Load A tile (128 rows x 16 k), store transposed As[k][m].
#pragma unroll
        for (int i = 0; i < 2; i++) {
            int s   = t * 2 + i;           // 0..511
            int row = s >> 2;              // 0..127
            int kq  = s & 3;               // 0..3 (16B chunk of the 64B k-seg)
            float4 v = *(const float4*)&X[(size_t)(m0 + row) * 256 + k0 + kq * 4];
            As[kq * 4 + 0][row] = v.x;
            As[kq * 4 + 1][row] = v.y;
            As[kq * 4 + 2][row] = v.z;
            As[kq * 4 + 3][row] = v.w;
        }
        // Load B tile (16 rows x 128 h), direct.
#pragma unroll
        for (int i = 0; i < 2; i++) {
            int s  = t * 2 + i;            // 0..511
            int kr = s >> 5;               // 0..15
            int hq = s & 31;               // 0..31
            float4 v = *(const float4*)&Wx[(size_t)(k0 + kr) * 256 + h0 + hq * 4];
            *(float4*)&Bs[kr][hq * 4] = v;
        }
        __syncthreads();

#pragma unroll
        for (int kk = 0; kk < 16; kk++) {
            // a: 16 consecutive rows for this warp -> 8 f32x2 pairs (broadcast LDS)
            const ulonglong2* ar = (const ulonglong2*)&As[kk][warp * 16];
            ulonglong2 q0 = ar[0], q1 = ar[1], q2 = ar[2], q3 = ar[3];
            ULL ap[8] = {q0.x, q0.y, q1.x, q1.y, q2.x, q2.y, q3.x, q3.y};
            // b: 4 cols for this lane, splatted
            float4 bv = *(const float4*)&Bs[kk][lane * 4];
            ULL bs0 = pk2(bv.x, bv.x), bs1 = pk2(bv.y, bv.y);
            ULL bs2 = pk2(bv.z, bv.z), bs3 = pk2(bv.w, bv.w);
#pragma unroll
            for (int p = 0; p < 8; p++) {
                acc[p][0] = f2fma(ap[p], bs0, acc[p][0]);
                acc[p][1] = f2fma(ap[p], bs1, acc[p][1]);
                acc[p][2] = f2fma(ap[p], bs2, acc[p][2]);
                acc[p][3] = f2fma(ap[p], bs3, acc[p][3]);
            }
        }
        __syncthreads();
    }

    // Epilogue: + bias, store two rows per pair (coalesced 512B/row/warp).
    float4 bb = *(const float4*)&bias[h0 + lane * 4];
#pragma unroll
    for (int p = 0; p < 8; p++) {
        float lo0, hi0, lo1, hi1, lo2, hi2, lo3, hi3;
        upk2(acc[p][0], lo0, hi0);
        upk2(acc[p][1], lo1, hi1);
        upk2(acc[p][2], lo2, hi2);
        upk2(acc[p][3], lo3, hi3);
        int m = m0 + warp * 16 + p * 2;
        float4 r0 = make_float4(lo0 + bb.x, lo1 + bb.y, lo2 + bb.z, lo3 + bb.w);
        float4 r1 = make_float4(hi0 + bb.x, hi1 + bb.y, hi2 + bb.z, hi3 + bb.w);
        *(float4*)&g_xw[(size_t)m * 256 + h0 + lane * 4]       = r0;
        *(float4*)&g_xw[(size_t)(m + 1) * 256 + h0 + lane * 4] = r1;
    }
}

// ---------------------------------------------------------------------------
// Kernel 2: recurrence. grid = 128 blocks, cluster (2,1,1).
// Block handles batch n = bx>>1, columns [r*128, r*128+128).
// 256 threads: j = t&127 (column), ks = t>>7 (k-half). Each thread holds
// Wh[ks*128 .. +127][jbase+j] as 64 f32x2 registers.
// ---------------------------------------------------------------------------
__global__ void __launch_bounds__(256, 1) __cluster_dims__(2, 1, 1)
rnn_scan(const float* __restrict__ h0g, const float* __restrict__ Wh,
         float* __restrict__ out) {
    __shared__ __align__(16) float h_buf[2][256];
    __shared__ float p_s[2][128];
    __shared__ __align__(8) ULL mbar;

    const int t     = threadIdx.x;
    const int n     = blockIdx.x >> 1;
    const int r     = blockIdx.x & 1;
    const int jbase = r * 128;
    const int j     = t & 127;
    const int ks    = t >> 7;

    // Register-resident weight slice: pairs along k.
    ULL W2[64];
#pragma unroll
    for (int k2 = 0; k2 < 64; k2++) {
        float w0 = Wh[(size_t)(ks * 128 + 2 * k2) * 256 + jbase + j];
        float w1 = Wh[(size_t)(ks * 128 + 2 * k2 + 1) * 256 + jbase + j];
        W2[k2] = pk2(w0, w1);
    }

    // Initial hidden state (each CTA keeps the full 256-vector).
    h_buf[0][t] = h0g[(size_t)n * 256 + t];

    const unsigned int bar_local = smem_u32(&mbar);
    if (t == 0) {
        asm volatile("mbarrier.init.shared.b64 [%0], %1;"
                     :: "r"(bar_local), "r"(128) : "memory");
    }
    // Cluster sync: mbarrier init + h_buf visible before any peer traffic.
    asm volatile("barrier.cluster.arrive.aligned;" ::: "memory");
    asm volatile("barrier.cluster.wait.aligned;" ::: "memory");

    const unsigned int peer = r ^ 1;
    unsigned int rem_h0 = 0, rem_h1 = 0, rem_bar;
    if (t < 128) {
        unsigned int lh0 = smem_u32(&h_buf[0][jbase + t]);
        unsigned int lh1 = smem_u32(&h_buf[1][jbase + t]);
        asm("mapa.shared::cluster.u32 %0, %1, %2;" : "=r"(rem_h0) : "r"(lh0), "r"(peer));
        asm("mapa.shared::cluster.u32 %0, %1, %2;" : "=r"(rem_h1) : "r"(lh1), "r"(peer));
    }
    asm("mapa.shared::cluster.u32 %0, %1, %2;" : "=r"(rem_bar) : "r"(bar_local), "r"(peer));

    const float* xwp = g_xw + (size_t)n * 512 * 256 + jbase;
    float xw_cur = (t < 128) ? xwp[t] : 0.f;

    for (int s = 0; s < 512; s++) {
        const int cur = s & 1;
        const int nxt = cur ^ 1;

        // Prefetch next step's input projection (hidden under the FMA chain).
        float xw_nxt = 0.f;
        if (t < 128) {
            int sn = (s + 1 < 512) ? (s + 1) : s;
            xw_nxt = xwp[(size_t)sn * 256 + t];
        }

        // Partial dot over this thread's 128 k's (two f32x2 chains).
        const ULL* hp = (const ULL*)&h_buf[cur][ks * 128];
        ULL a0 = 0ULL, a1 = 0ULL;
#pragma unroll
        for (int k2 = 0; k2 < 64; k2 += 2) {
            a0 = f2fma(hp[k2],     W2[k2],     a0);
            a1 = f2fma(hp[k2 + 1], W2[k2 + 1], a1);
        }
        ULL asum = f2add(a0, a1);
        float plo, phi;
        upk2(asum, plo, phi);
        p_s[ks][j] = plo + phi;
        __syncthreads();   // partials visible; all reads of h_buf[cur] done

        if (t < 128) {
            float pre = xw_cur + p_s[0][t] + p_s[1][t];
            float hn  = tanhf(pre);
            out[((size_t)n * 512 + s) * 256 + jbase + t] = hn;
            h_buf[nxt][jbase + t] = hn;                 // local copy
            unsigned int ra = (nxt == 0) ? rem_h0 : rem_h1;
            asm volatile("st.shared::cluster.f32 [%0], %1;"
                         :: "r"(ra), "f"(hn) : "memory");
            // Release-arrive on the peer's barrier orders our DSMEM store.
            asm volatile("mbarrier.arrive.release.cluster.shared::cluster.b64 _, [%0];"
                         :: "r"(rem_bar) : "memory");
        }
        xw_cur = xw_nxt;

        // Wait for the peer's 128 arrivals of this phase (acquire.cluster).
        {
            unsigned int par = (unsigned int)(s & 1);
            unsigned int done;
            asm volatile(
                "{ .reg .pred p; "
                "mbarrier.try_wait.parity.acquire.cluster.shared::cta.b64 p, [%1], %2; "
                "selp.b32 %0, 1, 0, p; }"
                : "=r"(done) : "r"(bar_local), "r"(par) : "memory");
            while (!done) {
                asm volatile(
                    "{ .reg .pred p; "
                    "mbarrier.try_wait.parity.acquire.cluster.shared::cta.b64 p, [%1], %2, 0x989680; "
                    "selp.b32 %0, 1, 0, p; }"
                    : "=r"(done) : "r"(bar_local), "r"(par) : "memory");
            }
        }
        __syncthreads();   // local h half visible to all threads
    }

    // Don't exit while the peer may still write into our SMEM.
    asm volatile("barrier.cluster.arrive.aligned;" ::: "memory");
    asm volatile("barrier.cluster.wait.aligned;" ::: "memory");
}

// ---------------------------------------------------------------------------
extern "C" void kernel_launch(void* const* d_in, const int* in_sizes, int n_in,
                              void* d_out, int out_size) {
    const float* x  = (const float*)d_in[0];  // (64,512,256)
    const float* h0 = (const float*)d_in[1];  // (64,256)
    const float* Wx = (const float*)d_in[2];  // (256,256)
    const float* Wh = (const float*)d_in[3];  // (256,256)
    const float* b  = (const float*)d_in[4];  // (256,)
    float* out = (float*)d_out;               // (64,512,256)

    dim3 g1(256, 2);   // M/128 x H/128
    gemm_xw<<<g1, 256>>>(x, Wx, b);
    rnn_scan<<<128, 256>>>(h0, Wh, out);
    (void)in_sizes; (void)n_in; (void)out_size;
}